// round 13
// baseline (speedup 1.0000x reference)
#include <cuda_runtime.h>
#include <math.h>
#include <stdint.h>

#define BB 2
#define NN 512
#define DD 64
#define HH 8
#define DHH 128

// ----------------- k_edge smem layout (floats) -----------------
#define OFF_ELOG   0        // 8*520 = 4160
#define OFF_WEP    4160     // 512  (g1-scaled We)
#define OFF_WGP    4672     // 512  (g1-scaled Wg)
#define OFF_Q      5184     // 64
#define OFF_SE     5248     // 8
#define OFF_CE     5256     // 8
#define OFF_SG     5264     // 8
#define OFF_CG     5272     // 8
#define OFF_CENT   5280     // 8
#define OFF_WPART  5288     // 64
#define OFF_ET     5352     // 128 x 68 staged e tile   (8704)
#define OFF_KT     14056    // 128 x 68 staged K tile   (8704)
#define EDGE_SMEM_FLOATS 22760
#define EDGE_SMEM_BYTES  (EDGE_SMEM_FLOATS*4)   // 91040 B

// ----------------- K3 (finish + mlp) smem layout (floats) -----------------
#define KA_OFF    0          // sA   128 x 68 fp32 (8704)
#define KW1_OFF   8704       // sW1  64 x 136 tf32 (permuted)
#define KH_OFF    17408      // sH   128 x 132 tf32
#define KW2_OFF   34304      // sW2  128 x 72 tf32 (permuted)
#define KB1_OFF   43520      // 128
#define KB2_OFF   43648      // 64
#define KWOE_OFF  43712      // 512  (Wo_e [8][64])
#define KEL_OFF   44224      // 1024 (Elog slice [8][128])
#define KG1_OFF   45248      // 64
#define KBE1_OFF  45312      // 64
#define KG2_OFF   45376      // 64
#define KBE2_OFF  45440      // 64
#define K3_SMEM_FLOATS 45504
#define K3_SMEM_BYTES  (K3_SMEM_FLOATS*4)   // 182016 B

__device__ __align__(16) float g_n1[BB*NN*DD];
__device__ __align__(16) float g_q [BB*NN*DD];
__device__ __align__(16) float g_k [BB*NN*DD];
__device__ __align__(16) float g_vt[BB*HH*8*NN];   // V transposed: [b][h][d][j]
__device__ __align__(16) float g_vc[BB*NN*DD];
__device__ __align__(16) float g_elog[(size_t)BB*HH*NN*NN];   // 16.8 MB

__device__ __forceinline__ uint32_t f2tf32(float x) {
    uint32_t r;
    asm("cvt.rna.tf32.f32 %0, %1;" : "=r"(r) : "f"(x));
    return r;
}

__device__ __forceinline__ void mma_tf32(float& c0, float& c1, float& c2, float& c3,
                                         uint32_t a0, uint32_t a1,
                                         uint32_t a2, uint32_t a3,
                                         uint32_t b0, uint32_t b1) {
    asm volatile(
        "mma.sync.aligned.m16n8k8.row.col.f32.tf32.tf32.f32 "
        "{%0,%1,%2,%3},{%4,%5,%6,%7},{%8,%9},{%0,%1,%2,%3};"
        : "+f"(c0), "+f"(c1), "+f"(c2), "+f"(c3)
        : "r"(a0), "r"(a1), "r"(a2), "r"(a3), "r"(b0), "r"(b1));
}

// packed dual FMA (Blackwell f32x2)
__device__ __forceinline__ void ffma2(uint64_t& acc, uint64_t a, uint64_t b) {
    asm("fma.rn.f32x2 %0, %1, %2, %0;" : "+l"(acc) : "l"(a), "l"(b));
}
__device__ __forceinline__ uint64_t pack2(float x) {
    uint64_t r;
    asm("mov.b64 %0, {%1, %1};" : "=l"(r) : "f"(x));
    return r;
}
__device__ __forceinline__ void unpack2(uint64_t v, float& lo, float& hi) {
    asm("mov.b64 {%0, %1}, %2;" : "=f"(lo), "=f"(hi) : "l"(v));
}

// ---------------------------------------------------------------------------
// K1: node LN + Q/K/V projection (V also stored transposed).
// ---------------------------------------------------------------------------
__global__ void k_node_prep(const float* __restrict__ n,
                            const float* __restrict__ Wq,
                            const float* __restrict__ Wk,
                            const float* __restrict__ Wv,
                            const float* __restrict__ lng,
                            const float* __restrict__ lnb)
{
    int row = blockIdx.x;
    int o = threadIdx.x;
    __shared__ float sx[DD];
    __shared__ float sn1[DD];
    sx[o] = n[row*DD + o];
    __syncthreads();
    float s = 0.f;
    #pragma unroll
    for (int k = 0; k < DD; k++) s += sx[k];
    float m = s * (1.f/DD);
    float v = 0.f;
    #pragma unroll
    for (int k = 0; k < DD; k++) { float d = sx[k]-m; v += d*d; }
    v *= (1.f/DD);
    float rstd = rsqrtf(v + 1e-5f);
    float n1 = (sx[o]-m)*rstd*lng[o] + lnb[o];
    sn1[o] = n1;
    g_n1[row*DD + o] = n1;
    __syncthreads();
    float q = 0.f, kk = 0.f, vv = 0.f;
    #pragma unroll
    for (int k = 0; k < DD; k++) {
        float a = sn1[k];
        q  += a * Wq[k*DD + o];
        kk += a * Wk[k*DD + o];
        vv += a * Wv[k*DD + o];
    }
    g_q[row*DD + o] = q;
    g_k[row*DD + o] = kk;
    int b = row >> 9;
    int j = row & 511;
    int h = o >> 3;
    int d = o & 7;
    g_vt[((b*HH + h)*8 + d)*NN + j] = vv;
}

// ---------------------------------------------------------------------------
// K2: edge attention, smem-staged chunks, packed f32x2 E/G accumulation.
// ---------------------------------------------------------------------------
__global__ void __launch_bounds__(256, 1)
k_edge(const float* __restrict__ e,
       const float* __restrict__ We, const float* __restrict__ Wg,
       const float* __restrict__ lg1, const float* __restrict__ lb1)
{
    extern __shared__ float sm[];
    float* sElog  = sm + OFF_ELOG;
    float* sWeP   = sm + OFF_WEP;
    float* sWgP   = sm + OFF_WGP;
    float* sQ     = sm + OFF_Q;
    float* sSe    = sm + OFF_SE;
    float* sCe    = sm + OFF_CE;
    float* sSg    = sm + OFF_SG;
    float* sCg    = sm + OFF_CG;
    float* sCent  = sm + OFF_CENT;
    float* sWpart = sm + OFF_WPART;
    float* sE     = sm + OFF_ET;
    float* sK     = sm + OFF_KT;

    const int i    = blockIdx.x;
    const int b    = blockIdx.y;
    const int tid  = threadIdx.x;
    const int lane = tid & 31;
    const int warp = tid >> 5;
    const int rowbn = b*NN + i;

    const int r    = tid >> 1;
    const int half = tid & 1;
    const int k0w  = half * 32;

    for (int t = tid; t < 512; t += 256) {
        int k = t >> 3;
        float g = lg1[k];
        sWeP[t] = g * We[t];
        sWgP[t] = g * Wg[t];
    }
    if (tid < 64) sQ[tid] = g_q[rowbn*DD + tid];
    __syncthreads();
    if (tid < 8) {
        float se=0.f, ce=0.f, sg=0.f, cg=0.f;
        for (int k = 0; k < 64; k++) {
            float bb = lb1[k];
            se += sWeP[k*8 + tid];
            sg += sWgP[k*8 + tid];
            ce += bb * We[k*8 + tid];
            cg += bb * Wg[k*8 + tid];
        }
        sSe[tid]=se; sCe[tid]=ce; sSg[tid]=sg; sCg[tid]=cg;
    }

    const float scale = 0.35355339059327373f;
    float gacc[HH];
    #pragma unroll
    for (int h = 0; h < HH; h++) gacc[h] = 0.f;

    for (int ch = 0; ch < 4; ch++) {
        const int j0 = ch*128;
        __syncthreads();
        for (int t = tid; t < 2048; t += 256) {
            int row = t >> 4, q = t & 15;
            *(float4*)(sE + row*68 + q*4) =
                *(const float4*)(e + ((size_t)rowbn*NN + j0 + row)*DD + q*4);
            *(float4*)(sK + row*68 + q*4) =
                *(const float4*)(g_k + ((size_t)b*NN + j0 + row)*DD + q*4);
        }
        __syncthreads();

        float s = 0.f, sq = 0.f;
        uint64_t E2[4] = {0ull,0ull,0ull,0ull};
        uint64_t G2[4] = {0ull,0ull,0ull,0ull};
        float ac0=0.f, ac1=0.f, ac2=0.f, ac3=0.f;

        const float4* xp = (const float4*)(sE + r*68 + k0w);
        const float4* kp = (const float4*)(sK + r*68 + k0w);
        const float4* qp = (const float4*)(sQ + k0w);

        #pragma unroll
        for (int q = 0; q < 8; q++) {
            float4 xv = xp[q];
            float4 kv = kp[q];
            float4 qv = qp[q];
            s  += (xv.x + xv.y) + (xv.z + xv.w);
            sq += (xv.x*xv.x + xv.y*xv.y) + (xv.z*xv.z + xv.w*xv.w);
            float dot = qv.x*kv.x + qv.y*kv.y + qv.z*kv.z + qv.w*kv.w;
            if (q < 2)      ac0 += dot;
            else if (q < 4) ac1 += dot;
            else if (q < 6) ac2 += dot;
            else            ac3 += dot;
            float xs[4] = {xv.x, xv.y, xv.z, xv.w};
            #pragma unroll
            for (int c = 0; c < 4; c++) {
                int k = k0w + q*4 + c;
                uint64_t xk2 = pack2(xs[c]);
                const uint64_t* we2 = (const uint64_t*)(sWeP + k*8);
                const uint64_t* wg2 = (const uint64_t*)(sWgP + k*8);
                ffma2(E2[0], xk2, we2[0]);
                ffma2(E2[1], xk2, we2[1]);
                ffma2(E2[2], xk2, we2[2]);
                ffma2(E2[3], xk2, we2[3]);
                ffma2(G2[0], xk2, wg2[0]);
                ffma2(G2[1], xk2, wg2[1]);
                ffma2(G2[2], xk2, wg2[2]);
                ffma2(G2[3], xk2, wg2[3]);
            }
        }

        float Eh[HH], Gh[HH];
        #pragma unroll
        for (int t2 = 0; t2 < 4; t2++) {
            unpack2(E2[t2], Eh[2*t2], Eh[2*t2+1]);
            unpack2(G2[t2], Gh[2*t2], Gh[2*t2+1]);
        }

        s  += __shfl_xor_sync(0xffffffffu, s, 1);
        sq += __shfl_xor_sync(0xffffffffu, sq, 1);
        #pragma unroll
        for (int h = 0; h < HH; h++) {
            Eh[h] += __shfl_xor_sync(0xffffffffu, Eh[h], 1);
            Gh[h] += __shfl_xor_sync(0xffffffffu, Gh[h], 1);
        }
        float p0 = __shfl_xor_sync(0xffffffffu, ac0, 1);
        float p1 = __shfl_xor_sync(0xffffffffu, ac1, 1);
        float p2 = __shfl_xor_sync(0xffffffffu, ac2, 1);
        float p3 = __shfl_xor_sync(0xffffffffu, ac3, 1);
        float qk0 = half ? p0 : ac0;
        float qk1 = half ? p1 : ac1;
        float qk2 = half ? p2 : ac2;
        float qk3 = half ? p3 : ac3;
        float qk4 = half ? ac0 : p0;
        float qk5 = half ? ac1 : p1;
        float qk6 = half ? ac2 : p2;
        float qk7 = half ? ac3 : p3;

        float m = s * (1.f/64.f);
        float var = sq * (1.f/64.f) - m*m;
        float rstd = rsqrtf(var + 1e-5f);

        if (half == 0) {
            const int j = j0 + r;
            float qks[8] = {qk0,qk1,qk2,qk3,qk4,qk5,qk6,qk7};
            #pragma unroll
            for (int h = 0; h < HH; h++) {
                float E = rstd*(Eh[h] - m*sSe[h]) + sCe[h];
                float G = rstd*(Gh[h] - m*sSg[h]) + sCg[h];
                float a = fminf(fmaxf(qks[h]*scale, -5.f), 5.f);
                sElog[h*520 + j] = a + E;
                gacc[h] += 1.f/(1.f + expf(-G));
            }
        }
    }

    #pragma unroll
    for (int h = 0; h < HH; h++) {
        #pragma unroll
        for (int off = 16; off > 0; off >>= 1)
            gacc[h] += __shfl_xor_sync(0xffffffffu, gacc[h], off);
    }
    if (lane == 0) {
        #pragma unroll
        for (int h = 0; h < HH; h++) sWpart[warp*8 + h] = gacc[h];
    }
    __syncthreads();
    if (tid < 8) {
        float ssum = 0.f;
        #pragma unroll
        for (int w = 0; w < 8; w++) ssum += sWpart[w*8 + tid];
        sCent[tid] = log1pf(ssum);
    }
    __syncthreads();

    {
        const int h = warp;
        const float* el = sElog + h*520;
        const float* vt = g_vt + (size_t)(b*HH + h)*8*NN;
        float mmax = -1e30f;
        for (int j = lane; j < NN; j += 32) mmax = fmaxf(mmax, el[j]);
        #pragma unroll
        for (int off = 16; off > 0; off >>= 1)
            mmax = fmaxf(mmax, __shfl_xor_sync(0xffffffffu, mmax, off));

        float denom = 0.f;
        float p0=0,p1=0,p2=0,p3=0,p4=0,p5=0,p6=0,p7=0;
        for (int j = lane; j < NN; j += 32) {
            float t = expf(el[j] - mmax);
            denom += t;
            p0 += t*vt[0*NN + j];
            p1 += t*vt[1*NN + j];
            p2 += t*vt[2*NN + j];
            p3 += t*vt[3*NN + j];
            p4 += t*vt[4*NN + j];
            p5 += t*vt[5*NN + j];
            p6 += t*vt[6*NN + j];
            p7 += t*vt[7*NN + j];
        }
        #pragma unroll
        for (int off = 16; off > 0; off >>= 1) {
            denom += __shfl_xor_sync(0xffffffffu, denom, off);
            p0 += __shfl_xor_sync(0xffffffffu, p0, off);
            p1 += __shfl_xor_sync(0xffffffffu, p1, off);
            p2 += __shfl_xor_sync(0xffffffffu, p2, off);
            p3 += __shfl_xor_sync(0xffffffffu, p3, off);
            p4 += __shfl_xor_sync(0xffffffffu, p4, off);
            p5 += __shfl_xor_sync(0xffffffffu, p5, off);
            p6 += __shfl_xor_sync(0xffffffffu, p6, off);
            p7 += __shfl_xor_sync(0xffffffffu, p7, off);
        }
        if (lane == 0) {
            float c = sCent[h] / denom;
            float* dst = g_vc + rowbn*DD + h*8;
            dst[0]=p0*c; dst[1]=p1*c; dst[2]=p2*c; dst[3]=p3*c;
            dst[4]=p4*c; dst[5]=p5*c; dst[6]=p6*c; dst[7]=p7*c;
        }
    }

    __syncthreads();
    for (int t = tid; t < HH*NN; t += 256) {
        int h = t >> 9, j = t & 511;
        g_elog[(((size_t)b*HH + h)*NN + i)*NN + j] = sElog[h*520 + j];
    }
}

// ---------------------------------------------------------------------------
// K3: fused edge finish + MLP. Permuted weight layout: B-fragments loaded
// as single LDS.128 (uint4) instead of 4 scalar LDS.
// ---------------------------------------------------------------------------
__global__ void __launch_bounds__(256, 1)
k_edge_finish_mlp(const float* __restrict__ e,
                  const float* __restrict__ WoE,
                  const float* __restrict__ lg1, const float* __restrict__ lb1,
                  const float* __restrict__ lg2, const float* __restrict__ lb2,
                  const float* __restrict__ W1, const float* __restrict__ b1,
                  const float* __restrict__ W2, const float* __restrict__ b2,
                  float* __restrict__ e_out)
{
    extern __shared__ float sm[];
    float*    sA   = sm + KA_OFF;
    uint32_t* sW1  = (uint32_t*)(sm + KW1_OFF);
    uint32_t* sH   = (uint32_t*)(sm + KH_OFF);
    uint32_t* sW2  = (uint32_t*)(sm + KW2_OFF);
    float*    sB1  = sm + KB1_OFF;
    float*    sB2  = sm + KB2_OFF;
    float*    sWoe = sm + KWOE_OFF;
    float*    sEl  = sm + KEL_OFF;
    float*    sG1  = sm + KG1_OFF;
    float*    sBe1 = sm + KBE1_OFF;
    float*    sG2  = sm + KG2_OFF;
    float*    sBe2 = sm + KBE2_OFF;

    const int tid  = threadIdx.x;
    const int lane = tid & 31;
    const int warp = tid >> 5;
    const int gid  = lane >> 2;
    const int tig  = lane & 3;

    const int bx = blockIdx.x;
    const int jc = bx & 3;
    const int i  = bx >> 2;
    const int b  = blockIdx.y;
    const int rowbn = b*NN + i;
    const size_t gj0 = (size_t)rowbn*NN + jc*128;

    // permuted W1: pos = k*136 + nc*32 + g*4 + nt   (u = nc*32 + nt*8 + g)
    for (int t = tid; t < 64*DHH; t += 256) {
        int k = t >> 7, u = t & 127;
        int nc = u >> 5, rem = u & 31, nt = rem >> 3, g = rem & 7;
        sW1[k*136 + nc*32 + g*4 + nt] = f2tf32(W1[t]);
    }
    // permuted W2: pos = u*72 + nc*32 + g*4 + nt   (c = nc*32 + nt*8 + g)
    for (int t = tid; t < DHH*64; t += 256) {
        int u = t >> 6, c = t & 63;
        int nc = c >> 5, rem = c & 31, nt = rem >> 3, g = rem & 7;
        sW2[u*72 + nc*32 + g*4 + nt] = f2tf32(W2[t]);
    }
    for (int t = tid; t < 512; t += 256) sWoe[t] = WoE[t];
    if (tid < 128) sB1[tid] = b1[tid];
    if (tid < 64) {
        sB2[tid]  = b2[tid];
        sG1[tid]  = lg1[tid]; sBe1[tid] = lb1[tid];
        sG2[tid]  = lg2[tid]; sBe2[tid] = lb2[tid];
    }
    for (int t = tid; t < 1024; t += 256) {
        int h = t >> 7, jl = t & 127;
        sEl[h*128 + jl] = g_elog[(((size_t)b*HH + h)*NN + i)*NN + jc*128 + jl];
    }
    for (int t = tid; t < 128*16; t += 256) {
        int row = t >> 4, q = t & 15;
        float4 v = *(const float4*)(e + (gj0 + row)*DD + q*4);
        *(float4*)(sA + row*68 + q*4) = v;
    }
    __syncthreads();

    // phase A: e3 = LN2( LN1(x) + El @ WoE ) in sA
    {
        const int r     = tid >> 1;
        const int halfc = tid & 1;
        const int c0    = halfc*32;

        float s = 0.f, sq = 0.f;
        #pragma unroll
        for (int c = 0; c < 32; c++) {
            float v = sA[r*68 + c0 + c];
            s += v; sq += v*v;
        }
        s  += __shfl_xor_sync(0xffffffffu, s, 1);
        sq += __shfl_xor_sync(0xffffffffu, sq, 1);
        float m = s*(1.f/64.f);
        float rstd = rsqrtf(sq*(1.f/64.f) - m*m + 1e-5f);

        float el0=sEl[r], el1=sEl[128+r], el2=sEl[256+r], el3=sEl[384+r];
        float el4=sEl[512+r], el5=sEl[640+r], el6=sEl[768+r], el7=sEl[896+r];

        float y[32];
        #pragma unroll
        for (int c = 0; c < 32; c++) {
            int k = c0 + c;
            float x = sA[r*68 + k];
            float a = (x - m)*rstd*sG1[k] + sBe1[k];
            a += el0*sWoe[k]       + el1*sWoe[64 + k]
               + el2*sWoe[128 + k] + el3*sWoe[192 + k]
               + el4*sWoe[256 + k] + el5*sWoe[320 + k]
               + el6*sWoe[384 + k] + el7*sWoe[448 + k];
            y[c] = a;
        }
        float s2 = 0.f, q2 = 0.f;
        #pragma unroll
        for (int c = 0; c < 32; c++) { s2 += y[c]; q2 += y[c]*y[c]; }
        s2 += __shfl_xor_sync(0xffffffffu, s2, 1);
        q2 += __shfl_xor_sync(0xffffffffu, q2, 1);
        float m2 = s2*(1.f/64.f);
        float rstd2 = rsqrtf(q2*(1.f/64.f) - m2*m2 + 1e-5f);
        #pragma unroll
        for (int c = 0; c < 32; c++) {
            int k = c0 + c;
            sA[r*68 + k] = (y[c] - m2)*rstd2*sG2[k] + sBe2[k];
        }
    }
    __syncthreads();

    // phase B: tf32 mma MLP with vectorized B loads
    const int row0 = warp*16 + gid;
    const int row1 = row0 + 8;

    uint32_t af0[8], af1[8], af2[8], af3[8];
    #pragma unroll
    for (int kt = 0; kt < 8; kt++) {
        int c0 = kt*8 + tig;
        af0[kt] = f2tf32(sA[row0*68 + c0]);
        af1[kt] = f2tf32(sA[row1*68 + c0]);
        af2[kt] = f2tf32(sA[row0*68 + c0 + 4]);
        af3[kt] = f2tf32(sA[row1*68 + c0 + 4]);
    }

    #pragma unroll
    for (int nc = 0; nc < 4; nc++) {
        float a00=0,a01=0,a02=0,a03=0;
        float a10=0,a11=0,a12=0,a13=0;
        float a20=0,a21=0,a22=0,a23=0;
        float a30=0,a31=0,a32=0,a33=0;
        #pragma unroll
        for (int kt = 0; kt < 8; kt++) {
            const uint4 bv0 = *(const uint4*)(sW1 + (kt*8 + tig)*136 + nc*32 + gid*4);
            const uint4 bv1 = *(const uint4*)(sW1 + (kt*8 + tig + 4)*136 + nc*32 + gid*4);
            mma_tf32(a00,a01,a02,a03, af0[kt],af1[kt],af2[kt],af3[kt], bv0.x,bv1.x);
            mma_tf32(a10,a11,a12,a13, af0[kt],af1[kt],af2[kt],af3[kt], bv0.y,bv1.y);
            mma_tf32(a20,a21,a22,a23, af0[kt],af1[kt],af2[kt],af3[kt], bv0.z,bv1.z);
            mma_tf32(a30,a31,a32,a33, af0[kt],af1[kt],af2[kt],af3[kt], bv0.w,bv1.w);
        }
        #pragma unroll
        for (int nt = 0; nt < 4; nt++) {
            float c0v, c1v, c2v, c3v;
            if (nt == 0)      { c0v=a00; c1v=a01; c2v=a02; c3v=a03; }
            else if (nt == 1) { c0v=a10; c1v=a11; c2v=a12; c3v=a13; }
            else if (nt == 2) { c0v=a20; c1v=a21; c2v=a22; c3v=a23; }
            else              { c0v=a30; c1v=a31; c2v=a32; c3v=a33; }
            int c = nc*32 + nt*8 + 2*tig;
            float bb0 = sB1[c], bb1 = sB1[c+1];
            sH[row0*132 + c    ] = f2tf32(fmaxf(c0v + bb0, 0.f));
            sH[row0*132 + c + 1] = f2tf32(fmaxf(c1v + bb1, 0.f));
            sH[row1*132 + c    ] = f2tf32(fmaxf(c2v + bb0, 0.f));
            sH[row1*132 + c + 1] = f2tf32(fmaxf(c3v + bb1, 0.f));
        }
    }
    __syncwarp();

    #pragma unroll
    for (int nc = 0; nc < 2; nc++) {
        float a00=0,a01=0,a02=0,a03=0;
        float a10=0,a11=0,a12=0,a13=0;
        float a20=0,a21=0,a22=0,a23=0;
        float a30=0,a31=0,a32=0,a33=0;
        #pragma unroll
        for (int kt = 0; kt < 16; kt++) {
            int c0 = kt*8 + tig;
            uint32_t h0 = sH[row0*132 + c0];
            uint32_t h1 = sH[row1*132 + c0];
            uint32_t h2 = sH[row0*132 + c0 + 4];
            uint32_t h3 = sH[row1*132 + c0 + 4];
            const uint4 bv0 = *(const uint4*)(sW2 + c0*72 + nc*32 + gid*4);
            const uint4 bv1 = *(const uint4*)(sW2 + (c0 + 4)*72 + nc*32 + gid*4);
            mma_tf32(a00,a01,a02,a03, h0,h1,h2,h3, bv0.x,bv1.x);
            mma_tf32(a10,a11,a12,a13, h0,h1,h2,h3, bv0.y,bv1.y);
            mma_tf32(a20,a21,a22,a23, h0,h1,h2,h3, bv0.z,bv1.z);
            mma_tf32(a30,a31,a32,a33, h0,h1,h2,h3, bv0.w,bv1.w);
        }
        #pragma unroll
        for (int nt = 0; nt < 4; nt++) {
            float c0v, c1v, c2v, c3v;
            if (nt == 0)      { c0v=a00; c1v=a01; c2v=a02; c3v=a03; }
            else if (nt == 1) { c0v=a10; c1v=a11; c2v=a12; c3v=a13; }
            else if (nt == 2) { c0v=a20; c1v=a21; c2v=a22; c3v=a23; }
            else              { c0v=a30; c1v=a31; c2v=a32; c3v=a33; }
            int c = nc*32 + nt*8 + 2*tig;
            float b20v = sB2[c], b21v = sB2[c+1];
            float r00 = sA[row0*68 + c    ] + fmaxf(c0v + b20v, 0.f);
            float r01 = sA[row0*68 + c + 1] + fmaxf(c1v + b21v, 0.f);
            float r10 = sA[row1*68 + c    ] + fmaxf(c2v + b20v, 0.f);
            float r11 = sA[row1*68 + c + 1] + fmaxf(c3v + b21v, 0.f);
            *(float2*)(e_out + (gj0 + row0)*DD + c) = make_float2(r00, r01);
            *(float2*)(e_out + (gj0 + row1)*DD + c) = make_float2(r10, r11);
        }
    }
}

// ---------------------------------------------------------------------------
// K4: node finish.
// ---------------------------------------------------------------------------
__global__ void k_node_finish(const float* __restrict__ Wo_n,
                              const float* __restrict__ lng,
                              const float* __restrict__ lnb,
                              const float* __restrict__ W1,
                              const float* __restrict__ Bi1,
                              const float* __restrict__ W2,
                              const float* __restrict__ Bi2,
                              float* __restrict__ n_out)
{
    int row = blockIdx.x;
    int o = threadIdx.x;
    __shared__ float svc[DD];
    __shared__ float sn2[DD];
    __shared__ float sn3[DD];
    __shared__ float sh[DHH];
    svc[o] = g_vc[row*DD + o];
    __syncthreads();
    float acc = 0.f;
    #pragma unroll
    for (int k = 0; k < DD; k++) acc += svc[k]*Wo_n[k*DD + o];
    float n2 = g_n1[row*DD + o] + acc;
    sn2[o] = n2;
    __syncthreads();
    float s = 0.f;
    #pragma unroll
    for (int k = 0; k < DD; k++) s += sn2[k];
    float m = s*(1.f/DD);
    float v = 0.f;
    #pragma unroll
    for (int k = 0; k < DD; k++) { float d = sn2[k]-m; v += d*d; }
    v *= (1.f/DD);
    float rstd = rsqrtf(v + 1e-5f);
    float n3 = (n2-m)*rstd*lng[o] + lnb[o];
    sn3[o] = n3;
    __syncthreads();
    #pragma unroll
    for (int uu = 0; uu < 2; uu++) {
        int u = o + uu*64;
        float h = Bi1[u];
        #pragma unroll
        for (int k = 0; k < DD; k++) h += sn3[k]*W1[k*DHH + u];
        sh[u] = fmaxf(h, 0.f);
    }
    __syncthreads();
    float oacc = Bi2[o];
    #pragma unroll
    for (int u = 0; u < DHH; u++) oacc += sh[u]*W2[u*DD + o];
    n_out[row*DD + o] = n3 + fmaxf(oacc, 0.f);
}

extern "C" void kernel_launch(void* const* d_in, const int* in_sizes, int n_in,
                              void* d_out, int out_size)
{
    const float* n       = (const float*)d_in[0];
    const float* e       = (const float*)d_in[1];
    const float* Wq      = (const float*)d_in[2];
    const float* Wk      = (const float*)d_in[3];
    const float* Wv      = (const float*)d_in[4];
    const float* Wo_n    = (const float*)d_in[5];
    const float* We      = (const float*)d_in[6];
    const float* Wg      = (const float*)d_in[7];
    const float* Wo_e    = (const float*)d_in[8];
    const float* ln_n1_g = (const float*)d_in[9];
    const float* ln_n1_b = (const float*)d_in[10];
    const float* ln_e1_g = (const float*)d_in[11];
    const float* ln_e1_b = (const float*)d_in[12];
    const float* ln_n2_g = (const float*)d_in[13];
    const float* ln_n2_b = (const float*)d_in[14];
    const float* ln_e2_g = (const float*)d_in[15];
    const float* ln_e2_b = (const float*)d_in[16];
    const float* mn_w1   = (const float*)d_in[17];
    const float* mn_b1   = (const float*)d_in[18];
    const float* mn_w2   = (const float*)d_in[19];
    const float* mn_b2   = (const float*)d_in[20];
    const float* me_w1   = (const float*)d_in[21];
    const float* me_b1   = (const float*)d_in[22];
    const float* me_w2   = (const float*)d_in[23];
    const float* me_b2   = (const float*)d_in[24];

    float* out   = (float*)d_out;
    float* n_out = out;
    float* e_out = out + BB*NN*DD;

    cudaFuncSetAttribute(k_edge, cudaFuncAttributeMaxDynamicSharedMemorySize, EDGE_SMEM_BYTES);
    cudaFuncSetAttribute(k_edge_finish_mlp, cudaFuncAttributeMaxDynamicSharedMemorySize, K3_SMEM_BYTES);

    k_node_prep<<<BB*NN, 64>>>(n, Wq, Wk, Wv, ln_n1_g, ln_n1_b);

    dim3 grid2(NN, BB);
    k_edge<<<grid2, 256, EDGE_SMEM_BYTES>>>(e, We, Wg, ln_e1_g, ln_e1_b);

    dim3 grid3(4*NN, BB);
    k_edge_finish_mlp<<<grid3, 256, K3_SMEM_BYTES>>>(e, Wo_e,
                                                     ln_e1_g, ln_e1_b,
                                                     ln_e2_g, ln_e2_b,
                                                     me_w1, me_b1, me_w2, me_b2,
                                                     e_out);

    k_node_finish<<<BB*NN, 64>>>(Wo_n, ln_n2_g, ln_n2_b,
                                 mn_w1, mn_b1, mn_w2, mn_b2, n_out);
}

// round 14
// speedup vs baseline: 1.0892x; 1.0892x over previous
#include <cuda_runtime.h>
#include <math.h>
#include <stdint.h>

#define BB 2
#define NN 512
#define DD 64
#define HH 8
#define DHH 128

// ----------------- k_edge smem layout (floats) -----------------
#define OFF_ELOG   0        // 8*520 = 4160
#define OFF_WEP    4160     // 512  (g1-scaled We)
#define OFF_WGP    4672     // 512  (g1-scaled Wg)
#define OFF_Q      5184     // 64
#define OFF_SE     5248     // 8
#define OFF_CE     5256     // 8
#define OFF_SG     5264     // 8
#define OFF_CG     5272     // 8
#define OFF_CENT   5280     // 8
#define OFF_WPART  5288     // 64
#define OFF_ET     5352     // 128 x 68 staged e tile   (8704)
#define OFF_KT     14056    // 128 x 68 staged K tile   (8704)
#define EDGE_SMEM_FLOATS 22760
#define EDGE_SMEM_BYTES  (EDGE_SMEM_FLOATS*4)   // 91040 B

// ----------------- K3 (finish + mlp) smem layout (floats) -----------------
#define KA_OFF    0          // sA   128 x 68 fp32 (8704)
#define KW1_OFF   8704       // sW1  64 x 136 tf32 (permuted)
#define KH_OFF    17408      // sH   128 x 132 tf32
#define KW2_OFF   34304      // sW2  128 x 72 tf32 (permuted)
#define KB1_OFF   43520      // 128
#define KB2_OFF   43648      // 64
#define KWOE_OFF  43712      // 512  (Wo_e [8][64])
#define KEL_OFF   44224      // 1024 (Elog slice [8][128])
#define KG1_OFF   45248      // 64
#define KBE1_OFF  45312      // 64
#define KG2_OFF   45376      // 64
#define KBE2_OFF  45440      // 64
#define K3_SMEM_FLOATS 45504
#define K3_SMEM_BYTES  (K3_SMEM_FLOATS*4)   // 182016 B

__device__ __align__(16) float g_n1[BB*NN*DD];
__device__ __align__(16) float g_q [BB*NN*DD];
__device__ __align__(16) float g_k [BB*NN*DD];
__device__ __align__(16) float g_vt[BB*HH*8*NN];   // V transposed: [b][h][d][j]
__device__ __align__(16) float g_vc[BB*NN*DD];
__device__ __align__(16) float g_elog[(size_t)BB*HH*NN*NN];   // 16.8 MB

__device__ __forceinline__ uint32_t f2tf32(float x) {
    uint32_t r;
    asm("cvt.rna.tf32.f32 %0, %1;" : "=r"(r) : "f"(x));
    return r;
}

__device__ __forceinline__ void mma_tf32(float& c0, float& c1, float& c2, float& c3,
                                         uint32_t a0, uint32_t a1,
                                         uint32_t a2, uint32_t a3,
                                         uint32_t b0, uint32_t b1) {
    asm volatile(
        "mma.sync.aligned.m16n8k8.row.col.f32.tf32.tf32.f32 "
        "{%0,%1,%2,%3},{%4,%5,%6,%7},{%8,%9},{%0,%1,%2,%3};"
        : "+f"(c0), "+f"(c1), "+f"(c2), "+f"(c3)
        : "r"(a0), "r"(a1), "r"(a2), "r"(a3), "r"(b0), "r"(b1));
}

// ---------------------------------------------------------------------------
// K1: node LN + Q/K/V projection (V also stored transposed).
// ---------------------------------------------------------------------------
__global__ void k_node_prep(const float* __restrict__ n,
                            const float* __restrict__ Wq,
                            const float* __restrict__ Wk,
                            const float* __restrict__ Wv,
                            const float* __restrict__ lng,
                            const float* __restrict__ lnb)
{
    int row = blockIdx.x;
    int o = threadIdx.x;
    __shared__ float sx[DD];
    __shared__ float sn1[DD];
    sx[o] = n[row*DD + o];
    __syncthreads();
    float s = 0.f;
    #pragma unroll
    for (int k = 0; k < DD; k++) s += sx[k];
    float m = s * (1.f/DD);
    float v = 0.f;
    #pragma unroll
    for (int k = 0; k < DD; k++) { float d = sx[k]-m; v += d*d; }
    v *= (1.f/DD);
    float rstd = rsqrtf(v + 1e-5f);
    float n1 = (sx[o]-m)*rstd*lng[o] + lnb[o];
    sn1[o] = n1;
    g_n1[row*DD + o] = n1;
    __syncthreads();
    float q = 0.f, kk = 0.f, vv = 0.f;
    #pragma unroll
    for (int k = 0; k < DD; k++) {
        float a = sn1[k];
        q  += a * Wq[k*DD + o];
        kk += a * Wk[k*DD + o];
        vv += a * Wv[k*DD + o];
    }
    g_q[row*DD + o] = q;
    g_k[row*DD + o] = kk;
    int b = row >> 9;
    int j = row & 511;
    int h = o >> 3;
    int d = o & 7;
    g_vt[((b*HH + h)*8 + d)*NN + j] = vv;
}

// ---------------------------------------------------------------------------
// K2: edge attention, smem-staged coalesced chunks (R12 version, scalar FFMA).
// ---------------------------------------------------------------------------
__global__ void __launch_bounds__(256, 1)
k_edge(const float* __restrict__ e,
       const float* __restrict__ We, const float* __restrict__ Wg,
       const float* __restrict__ lg1, const float* __restrict__ lb1)
{
    extern __shared__ float sm[];
    float* sElog  = sm + OFF_ELOG;
    float* sWeP   = sm + OFF_WEP;
    float* sWgP   = sm + OFF_WGP;
    float* sQ     = sm + OFF_Q;
    float* sSe    = sm + OFF_SE;
    float* sCe    = sm + OFF_CE;
    float* sSg    = sm + OFF_SG;
    float* sCg    = sm + OFF_CG;
    float* sCent  = sm + OFF_CENT;
    float* sWpart = sm + OFF_WPART;
    float* sE     = sm + OFF_ET;
    float* sK     = sm + OFF_KT;

    const int i    = blockIdx.x;
    const int b    = blockIdx.y;
    const int tid  = threadIdx.x;
    const int lane = tid & 31;
    const int warp = tid >> 5;
    const int rowbn = b*NN + i;

    const int r    = tid >> 1;
    const int half = tid & 1;
    const int k0w  = half * 32;

    for (int t = tid; t < 512; t += 256) {
        int k = t >> 3;
        float g = lg1[k];
        sWeP[t] = g * We[t];
        sWgP[t] = g * Wg[t];
    }
    if (tid < 64) sQ[tid] = g_q[rowbn*DD + tid];
    __syncthreads();
    if (tid < 8) {
        float se=0.f, ce=0.f, sg=0.f, cg=0.f;
        for (int k = 0; k < 64; k++) {
            float bb = lb1[k];
            se += sWeP[k*8 + tid];
            sg += sWgP[k*8 + tid];
            ce += bb * We[k*8 + tid];
            cg += bb * Wg[k*8 + tid];
        }
        sSe[tid]=se; sCe[tid]=ce; sSg[tid]=sg; sCg[tid]=cg;
    }

    const float scale = 0.35355339059327373f;
    float gacc[HH];
    #pragma unroll
    for (int h = 0; h < HH; h++) gacc[h] = 0.f;

    for (int ch = 0; ch < 4; ch++) {
        const int j0 = ch*128;
        __syncthreads();
        for (int t = tid; t < 2048; t += 256) {
            int row = t >> 4, q = t & 15;
            *(float4*)(sE + row*68 + q*4) =
                *(const float4*)(e + ((size_t)rowbn*NN + j0 + row)*DD + q*4);
            *(float4*)(sK + row*68 + q*4) =
                *(const float4*)(g_k + ((size_t)b*NN + j0 + row)*DD + q*4);
        }
        __syncthreads();

        float s = 0.f, sq = 0.f;
        float Eh[HH], Gh[HH];
        #pragma unroll
        for (int h = 0; h < HH; h++) { Eh[h]=0.f; Gh[h]=0.f; }
        float ac0=0.f, ac1=0.f, ac2=0.f, ac3=0.f;

        const float4* xp = (const float4*)(sE + r*68 + k0w);
        const float4* kp = (const float4*)(sK + r*68 + k0w);
        const float4* qp = (const float4*)(sQ + k0w);

        #pragma unroll
        for (int q = 0; q < 8; q++) {
            float4 xv = xp[q];
            float4 kv = kp[q];
            float4 qv = qp[q];
            s  += (xv.x + xv.y) + (xv.z + xv.w);
            sq += (xv.x*xv.x + xv.y*xv.y) + (xv.z*xv.z + xv.w*xv.w);
            float dot = qv.x*kv.x + qv.y*kv.y + qv.z*kv.z + qv.w*kv.w;
            if (q < 2)      ac0 += dot;
            else if (q < 4) ac1 += dot;
            else if (q < 6) ac2 += dot;
            else            ac3 += dot;
            float xs[4] = {xv.x, xv.y, xv.z, xv.w};
            #pragma unroll
            for (int c = 0; c < 4; c++) {
                int k = k0w + q*4 + c;
                float xk = xs[c];
                const float4* we = (const float4*)(sWeP + k*8);
                const float4* wg = (const float4*)(sWgP + k*8);
                float4 a0 = we[0], a1 = we[1];
                float4 c0 = wg[0], c1 = wg[1];
                Eh[0]+=xk*a0.x; Eh[1]+=xk*a0.y; Eh[2]+=xk*a0.z; Eh[3]+=xk*a0.w;
                Eh[4]+=xk*a1.x; Eh[5]+=xk*a1.y; Eh[6]+=xk*a1.z; Eh[7]+=xk*a1.w;
                Gh[0]+=xk*c0.x; Gh[1]+=xk*c0.y; Gh[2]+=xk*c0.z; Gh[3]+=xk*c0.w;
                Gh[4]+=xk*c1.x; Gh[5]+=xk*c1.y; Gh[6]+=xk*c1.z; Gh[7]+=xk*c1.w;
            }
        }

        s  += __shfl_xor_sync(0xffffffffu, s, 1);
        sq += __shfl_xor_sync(0xffffffffu, sq, 1);
        #pragma unroll
        for (int h = 0; h < HH; h++) {
            Eh[h] += __shfl_xor_sync(0xffffffffu, Eh[h], 1);
            Gh[h] += __shfl_xor_sync(0xffffffffu, Gh[h], 1);
        }
        float p0 = __shfl_xor_sync(0xffffffffu, ac0, 1);
        float p1 = __shfl_xor_sync(0xffffffffu, ac1, 1);
        float p2 = __shfl_xor_sync(0xffffffffu, ac2, 1);
        float p3 = __shfl_xor_sync(0xffffffffu, ac3, 1);
        float qk0 = half ? p0 : ac0;
        float qk1 = half ? p1 : ac1;
        float qk2 = half ? p2 : ac2;
        float qk3 = half ? p3 : ac3;
        float qk4 = half ? ac0 : p0;
        float qk5 = half ? ac1 : p1;
        float qk6 = half ? ac2 : p2;
        float qk7 = half ? ac3 : p3;

        float m = s * (1.f/64.f);
        float var = sq * (1.f/64.f) - m*m;
        float rstd = rsqrtf(var + 1e-5f);

        if (half == 0) {
            const int j = j0 + r;
            float qks[8] = {qk0,qk1,qk2,qk3,qk4,qk5,qk6,qk7};
            #pragma unroll
            for (int h = 0; h < HH; h++) {
                float E = rstd*(Eh[h] - m*sSe[h]) + sCe[h];
                float G = rstd*(Gh[h] - m*sSg[h]) + sCg[h];
                float a = fminf(fmaxf(qks[h]*scale, -5.f), 5.f);
                sElog[h*520 + j] = a + E;
                gacc[h] += 1.f/(1.f + expf(-G));
            }
        }
    }

    #pragma unroll
    for (int h = 0; h < HH; h++) {
        #pragma unroll
        for (int off = 16; off > 0; off >>= 1)
            gacc[h] += __shfl_xor_sync(0xffffffffu, gacc[h], off);
    }
    if (lane == 0) {
        #pragma unroll
        for (int h = 0; h < HH; h++) sWpart[warp*8 + h] = gacc[h];
    }
    __syncthreads();
    if (tid < 8) {
        float ssum = 0.f;
        #pragma unroll
        for (int w = 0; w < 8; w++) ssum += sWpart[w*8 + tid];
        sCent[tid] = log1pf(ssum);
    }
    __syncthreads();

    {
        const int h = warp;
        const float* el = sElog + h*520;
        const float* vt = g_vt + (size_t)(b*HH + h)*8*NN;
        float mmax = -1e30f;
        for (int j = lane; j < NN; j += 32) mmax = fmaxf(mmax, el[j]);
        #pragma unroll
        for (int off = 16; off > 0; off >>= 1)
            mmax = fmaxf(mmax, __shfl_xor_sync(0xffffffffu, mmax, off));

        float denom = 0.f;
        float p0=0,p1=0,p2=0,p3=0,p4=0,p5=0,p6=0,p7=0;
        for (int j = lane; j < NN; j += 32) {
            float t = expf(el[j] - mmax);
            denom += t;
            p0 += t*vt[0*NN + j];
            p1 += t*vt[1*NN + j];
            p2 += t*vt[2*NN + j];
            p3 += t*vt[3*NN + j];
            p4 += t*vt[4*NN + j];
            p5 += t*vt[5*NN + j];
            p6 += t*vt[6*NN + j];
            p7 += t*vt[7*NN + j];
        }
        #pragma unroll
        for (int off = 16; off > 0; off >>= 1) {
            denom += __shfl_xor_sync(0xffffffffu, denom, off);
            p0 += __shfl_xor_sync(0xffffffffu, p0, off);
            p1 += __shfl_xor_sync(0xffffffffu, p1, off);
            p2 += __shfl_xor_sync(0xffffffffu, p2, off);
            p3 += __shfl_xor_sync(0xffffffffu, p3, off);
            p4 += __shfl_xor_sync(0xffffffffu, p4, off);
            p5 += __shfl_xor_sync(0xffffffffu, p5, off);
            p6 += __shfl_xor_sync(0xffffffffu, p6, off);
            p7 += __shfl_xor_sync(0xffffffffu, p7, off);
        }
        if (lane == 0) {
            float c = sCent[h] / denom;
            float* dst = g_vc + rowbn*DD + h*8;
            dst[0]=p0*c; dst[1]=p1*c; dst[2]=p2*c; dst[3]=p3*c;
            dst[4]=p4*c; dst[5]=p5*c; dst[6]=p6*c; dst[7]=p7*c;
        }
    }

    __syncthreads();
    for (int t = tid; t < HH*NN; t += 256) {
        int h = t >> 9, j = t & 511;
        g_elog[(((size_t)b*HH + h)*NN + i)*NN + j] = sElog[h*520 + j];
    }
}

// ---------------------------------------------------------------------------
// K3: fused edge finish + MLP with permuted weight layout (vectorized B loads).
// ---------------------------------------------------------------------------
__global__ void __launch_bounds__(256, 1)
k_edge_finish_mlp(const float* __restrict__ e,
                  const float* __restrict__ WoE,
                  const float* __restrict__ lg1, const float* __restrict__ lb1,
                  const float* __restrict__ lg2, const float* __restrict__ lb2,
                  const float* __restrict__ W1, const float* __restrict__ b1,
                  const float* __restrict__ W2, const float* __restrict__ b2,
                  float* __restrict__ e_out)
{
    extern __shared__ float sm[];
    float*    sA   = sm + KA_OFF;
    uint32_t* sW1  = (uint32_t*)(sm + KW1_OFF);
    uint32_t* sH   = (uint32_t*)(sm + KH_OFF);
    uint32_t* sW2  = (uint32_t*)(sm + KW2_OFF);
    float*    sB1  = sm + KB1_OFF;
    float*    sB2  = sm + KB2_OFF;
    float*    sWoe = sm + KWOE_OFF;
    float*    sEl  = sm + KEL_OFF;
    float*    sG1  = sm + KG1_OFF;
    float*    sBe1 = sm + KBE1_OFF;
    float*    sG2  = sm + KG2_OFF;
    float*    sBe2 = sm + KBE2_OFF;

    const int tid  = threadIdx.x;
    const int lane = tid & 31;
    const int warp = tid >> 5;
    const int gid  = lane >> 2;
    const int tig  = lane & 3;

    const int bx = blockIdx.x;
    const int jc = bx & 3;
    const int i  = bx >> 2;
    const int b  = blockIdx.y;
    const int rowbn = b*NN + i;
    const size_t gj0 = (size_t)rowbn*NN + jc*128;

    // permuted W1: pos = k*136 + nc*32 + g*4 + nt   (u = nc*32 + nt*8 + g)
    for (int t = tid; t < 64*DHH; t += 256) {
        int k = t >> 7, u = t & 127;
        int nc = u >> 5, rem = u & 31, nt = rem >> 3, g = rem & 7;
        sW1[k*136 + nc*32 + g*4 + nt] = f2tf32(W1[t]);
    }
    // permuted W2: pos = u*72 + nc*32 + g*4 + nt   (c = nc*32 + nt*8 + g)
    for (int t = tid; t < DHH*64; t += 256) {
        int u = t >> 6, c = t & 63;
        int nc = c >> 5, rem = c & 31, nt = rem >> 3, g = rem & 7;
        sW2[u*72 + nc*32 + g*4 + nt] = f2tf32(W2[t]);
    }
    for (int t = tid; t < 512; t += 256) sWoe[t] = WoE[t];
    if (tid < 128) sB1[tid] = b1[tid];
    if (tid < 64) {
        sB2[tid]  = b2[tid];
        sG1[tid]  = lg1[tid]; sBe1[tid] = lb1[tid];
        sG2[tid]  = lg2[tid]; sBe2[tid] = lb2[tid];
    }
    for (int t = tid; t < 1024; t += 256) {
        int h = t >> 7, jl = t & 127;
        sEl[h*128 + jl] = g_elog[(((size_t)b*HH + h)*NN + i)*NN + jc*128 + jl];
    }
    for (int t = tid; t < 128*16; t += 256) {
        int row = t >> 4, q = t & 15;
        float4 v = *(const float4*)(e + (gj0 + row)*DD + q*4);
        *(float4*)(sA + row*68 + q*4) = v;
    }
    __syncthreads();

    // phase A: e3 = LN2( LN1(x) + El @ WoE ) in sA
    {
        const int r     = tid >> 1;
        const int halfc = tid & 1;
        const int c0    = halfc*32;

        float s = 0.f, sq = 0.f;
        #pragma unroll
        for (int c = 0; c < 32; c++) {
            float v = sA[r*68 + c0 + c];
            s += v; sq += v*v;
        }
        s  += __shfl_xor_sync(0xffffffffu, s, 1);
        sq += __shfl_xor_sync(0xffffffffu, sq, 1);
        float m = s*(1.f/64.f);
        float rstd = rsqrtf(sq*(1.f/64.f) - m*m + 1e-5f);

        float el0=sEl[r], el1=sEl[128+r], el2=sEl[256+r], el3=sEl[384+r];
        float el4=sEl[512+r], el5=sEl[640+r], el6=sEl[768+r], el7=sEl[896+r];

        float y[32];
        #pragma unroll
        for (int c = 0; c < 32; c++) {
            int k = c0 + c;
            float x = sA[r*68 + k];
            float a = (x - m)*rstd*sG1[k] + sBe1[k];
            a += el0*sWoe[k]       + el1*sWoe[64 + k]
               + el2*sWoe[128 + k] + el3*sWoe[192 + k]
               + el4*sWoe[256 + k] + el5*sWoe[320 + k]
               + el6*sWoe[384 + k] + el7*sWoe[448 + k];
            y[c] = a;
        }
        float s2 = 0.f, q2 = 0.f;
        #pragma unroll
        for (int c = 0; c < 32; c++) { s2 += y[c]; q2 += y[c]*y[c]; }
        s2 += __shfl_xor_sync(0xffffffffu, s2, 1);
        q2 += __shfl_xor_sync(0xffffffffu, q2, 1);
        float m2 = s2*(1.f/64.f);
        float rstd2 = rsqrtf(q2*(1.f/64.f) - m2*m2 + 1e-5f);
        #pragma unroll
        for (int c = 0; c < 32; c++) {
            int k = c0 + c;
            sA[r*68 + k] = (y[c] - m2)*rstd2*sG2[k] + sBe2[k];
        }
    }
    __syncthreads();

    // phase B: tf32 mma MLP with vectorized B loads
    const int row0 = warp*16 + gid;
    const int row1 = row0 + 8;

    uint32_t af0[8], af1[8], af2[8], af3[8];
    #pragma unroll
    for (int kt = 0; kt < 8; kt++) {
        int c0 = kt*8 + tig;
        af0[kt] = f2tf32(sA[row0*68 + c0]);
        af1[kt] = f2tf32(sA[row1*68 + c0]);
        af2[kt] = f2tf32(sA[row0*68 + c0 + 4]);
        af3[kt] = f2tf32(sA[row1*68 + c0 + 4]);
    }

    #pragma unroll
    for (int nc = 0; nc < 4; nc++) {
        float a00=0,a01=0,a02=0,a03=0;
        float a10=0,a11=0,a12=0,a13=0;
        float a20=0,a21=0,a22=0,a23=0;
        float a30=0,a31=0,a32=0,a33=0;
        #pragma unroll
        for (int kt = 0; kt < 8; kt++) {
            const uint4 bv0 = *(const uint4*)(sW1 + (kt*8 + tig)*136 + nc*32 + gid*4);
            const uint4 bv1 = *(const uint4*)(sW1 + (kt*8 + tig + 4)*136 + nc*32 + gid*4);
            mma_tf32(a00,a01,a02,a03, af0[kt],af1[kt],af2[kt],af3[kt], bv0.x,bv1.x);
            mma_tf32(a10,a11,a12,a13, af0[kt],af1[kt],af2[kt],af3[kt], bv0.y,bv1.y);
            mma_tf32(a20,a21,a22,a23, af0[kt],af1[kt],af2[kt],af3[kt], bv0.z,bv1.z);
            mma_tf32(a30,a31,a32,a33, af0[kt],af1[kt],af2[kt],af3[kt], bv0.w,bv1.w);
        }
        #pragma unroll
        for (int nt = 0; nt < 4; nt++) {
            float c0v, c1v, c2v, c3v;
            if (nt == 0)      { c0v=a00; c1v=a01; c2v=a02; c3v=a03; }
            else if (nt == 1) { c0v=a10; c1v=a11; c2v=a12; c3v=a13; }
            else if (nt == 2) { c0v=a20; c1v=a21; c2v=a22; c3v=a23; }
            else              { c0v=a30; c1v=a31; c2v=a32; c3v=a33; }
            int c = nc*32 + nt*8 + 2*tig;
            float bb0 = sB1[c], bb1 = sB1[c+1];
            sH[row0*132 + c    ] = f2tf32(fmaxf(c0v + bb0, 0.f));
            sH[row0*132 + c + 1] = f2tf32(fmaxf(c1v + bb1, 0.f));
            sH[row1*132 + c    ] = f2tf32(fmaxf(c2v + bb0, 0.f));
            sH[row1*132 + c + 1] = f2tf32(fmaxf(c3v + bb1, 0.f));
        }
    }
    __syncwarp();

    #pragma unroll
    for (int nc = 0; nc < 2; nc++) {
        float a00=0,a01=0,a02=0,a03=0;
        float a10=0,a11=0,a12=0,a13=0;
        float a20=0,a21=0,a22=0,a23=0;
        float a30=0,a31=0,a32=0,a33=0;
        #pragma unroll
        for (int kt = 0; kt < 16; kt++) {
            int c0 = kt*8 + tig;
            uint32_t h0 = sH[row0*132 + c0];
            uint32_t h1 = sH[row1*132 + c0];
            uint32_t h2 = sH[row0*132 + c0 + 4];
            uint32_t h3 = sH[row1*132 + c0 + 4];
            const uint4 bv0 = *(const uint4*)(sW2 + c0*72 + nc*32 + gid*4);
            const uint4 bv1 = *(const uint4*)(sW2 + (c0 + 4)*72 + nc*32 + gid*4);
            mma_tf32(a00,a01,a02,a03, h0,h1,h2,h3, bv0.x,bv1.x);
            mma_tf32(a10,a11,a12,a13, h0,h1,h2,h3, bv0.y,bv1.y);
            mma_tf32(a20,a21,a22,a23, h0,h1,h2,h3, bv0.z,bv1.z);
            mma_tf32(a30,a31,a32,a33, h0,h1,h2,h3, bv0.w,bv1.w);
        }
        #pragma unroll
        for (int nt = 0; nt < 4; nt++) {
            float c0v, c1v, c2v, c3v;
            if (nt == 0)      { c0v=a00; c1v=a01; c2v=a02; c3v=a03; }
            else if (nt == 1) { c0v=a10; c1v=a11; c2v=a12; c3v=a13; }
            else if (nt == 2) { c0v=a20; c1v=a21; c2v=a22; c3v=a23; }
            else              { c0v=a30; c1v=a31; c2v=a32; c3v=a33; }
            int c = nc*32 + nt*8 + 2*tig;
            float b20v = sB2[c], b21v = sB2[c+1];
            float r00 = sA[row0*68 + c    ] + fmaxf(c0v + b20v, 0.f);
            float r01 = sA[row0*68 + c + 1] + fmaxf(c1v + b21v, 0.f);
            float r10 = sA[row1*68 + c    ] + fmaxf(c2v + b20v, 0.f);
            float r11 = sA[row1*68 + c + 1] + fmaxf(c3v + b21v, 0.f);
            *(float2*)(e_out + (gj0 + row0)*DD + c) = make_float2(r00, r01);
            *(float2*)(e_out + (gj0 + row1)*DD + c) = make_float2(r10, r11);
        }
    }
}

// ---------------------------------------------------------------------------
// K4: node finish.
// ---------------------------------------------------------------------------
__global__ void k_node_finish(const float* __restrict__ Wo_n,
                              const float* __restrict__ lng,
                              const float* __restrict__ lnb,
                              const float* __restrict__ W1,
                              const float* __restrict__ Bi1,
                              const float* __restrict__ W2,
                              const float* __restrict__ Bi2,
                              float* __restrict__ n_out)
{
    int row = blockIdx.x;
    int o = threadIdx.x;
    __shared__ float svc[DD];
    __shared__ float sn2[DD];
    __shared__ float sn3[DD];
    __shared__ float sh[DHH];
    svc[o] = g_vc[row*DD + o];
    __syncthreads();
    float acc = 0.f;
    #pragma unroll
    for (int k = 0; k < DD; k++) acc += svc[k]*Wo_n[k*DD + o];
    float n2 = g_n1[row*DD + o] + acc;
    sn2[o] = n2;
    __syncthreads();
    float s = 0.f;
    #pragma unroll
    for (int k = 0; k < DD; k++) s += sn2[k];
    float m = s*(1.f/DD);
    float v = 0.f;
    #pragma unroll
    for (int k = 0; k < DD; k++) { float d = sn2[k]-m; v += d*d; }
    v *= (1.f/DD);
    float rstd = rsqrtf(v + 1e-5f);
    float n3 = (n2-m)*rstd*lng[o] + lnb[o];
    sn3[o] = n3;
    __syncthreads();
    #pragma unroll
    for (int uu = 0; uu < 2; uu++) {
        int u = o + uu*64;
        float h = Bi1[u];
        #pragma unroll
        for (int k = 0; k < DD; k++) h += sn3[k]*W1[k*DHH + u];
        sh[u] = fmaxf(h, 0.f);
    }
    __syncthreads();
    float oacc = Bi2[o];
    #pragma unroll
    for (int u = 0; u < DHH; u++) oacc += sh[u]*W2[u*DD + o];
    n_out[row*DD + o] = n3 + fmaxf(oacc, 0.f);
}

extern "C" void kernel_launch(void* const* d_in, const int* in_sizes, int n_in,
                              void* d_out, int out_size)
{
    const float* n       = (const float*)d_in[0];
    const float* e       = (const float*)d_in[1];
    const float* Wq      = (const float*)d_in[2];
    const float* Wk      = (const float*)d_in[3];
    const float* Wv      = (const float*)d_in[4];
    const float* Wo_n    = (const float*)d_in[5];
    const float* We      = (const float*)d_in[6];
    const float* Wg      = (const float*)d_in[7];
    const float* Wo_e    = (const float*)d_in[8];
    const float* ln_n1_g = (const float*)d_in[9];
    const float* ln_n1_b = (const float*)d_in[10];
    const float* ln_e1_g = (const float*)d_in[11];
    const float* ln_e1_b = (const float*)d_in[12];
    const float* ln_n2_g = (const float*)d_in[13];
    const float* ln_n2_b = (const float*)d_in[14];
    const float* ln_e2_g = (const float*)d_in[15];
    const float* ln_e2_b = (const float*)d_in[16];
    const float* mn_w1   = (const float*)d_in[17];
    const float* mn_b1   = (const float*)d_in[18];
    const float* mn_w2   = (const float*)d_in[19];
    const float* mn_b2   = (const float*)d_in[20];
    const float* me_w1   = (const float*)d_in[21];
    const float* me_b1   = (const float*)d_in[22];
    const float* me_w2   = (const float*)d_in[23];
    const float* me_b2   = (const float*)d_in[24];

    float* out   = (float*)d_out;
    float* n_out = out;
    float* e_out = out + BB*NN*DD;

    cudaFuncSetAttribute(k_edge, cudaFuncAttributeMaxDynamicSharedMemorySize, EDGE_SMEM_BYTES);
    cudaFuncSetAttribute(k_edge_finish_mlp, cudaFuncAttributeMaxDynamicSharedMemorySize, K3_SMEM_BYTES);

    k_node_prep<<<BB*NN, 64>>>(n, Wq, Wk, Wv, ln_n1_g, ln_n1_b);

    dim3 grid2(NN, BB);
    k_edge<<<grid2, 256, EDGE_SMEM_BYTES>>>(e, We, Wg, ln_e1_g, ln_e1_b);

    dim3 grid3(4*NN, BB);
    k_edge_finish_mlp<<<grid3, 256, K3_SMEM_BYTES>>>(e, Wo_e,
                                                     ln_e1_g, ln_e1_b,
                                                     ln_e2_g, ln_e2_b,
                                                     me_w1, me_b1, me_w2, me_b2,
                                                     e_out);

    k_node_finish<<<BB*NN, 64>>>(Wo_n, ln_n2_g, ln_n2_b,
                                 mn_w1, mn_b1, mn_w2, mn_b2, n_out);
}